// round 6
// baseline (speedup 1.0000x reference)
#include <cuda_runtime.h>
#include <cuda_fp16.h>

#define B_SZ    512
#define FEATS   30
#define NNZ     (B_SZ * FEATS)
#define FT_OUT  512
#define N_FEAT  40960
#define N_VFEAT 640
#define KP      (FT_OUT / 2)     // 256 k-pairs
#define HALF_C  (N_FEAT / 2)     // 20480 columns per half (multiple of 640)

// Packed indices, feature-major: g_packed[f*B + b] = stm_col | (nstm_col<<16)
__device__ unsigned g_packed[NNZ];
__device__ __half   g_vals[NNZ];
// Partial accumulators: [half][kp][b], float2 = (k0, k1). 2 MB each.
__device__ float2   g_accs[2][KP][B_SZ];
__device__ float2   g_accn[2][KP][B_SZ];

// Dynamic smem: __half2 sft2[HALF_C] (pair-interleaved fused table),
//               __half2 sfft2[N_VFEAT]
#define SMEM_BYTES ((HALF_C + N_VFEAT) * 4)

static __device__ __forceinline__ unsigned h2u(__half2 h) {
    return *reinterpret_cast<unsigned*>(&h);
}

// ---------------------------------------------------------------------------
// Kernel 0: prepass. Pack cols into u32, values into fp16, feature-major.
// Runs concurrently with the main kernel's streaming phase via PDL.
// ---------------------------------------------------------------------------
__global__ void __launch_bounds__(256) pack_idx_kernel(
    const int*   __restrict__ stm_idx,    // [2, NNZ]; cols at offset NNZ
    const int*   __restrict__ nstm_idx,   // [2, NNZ]
    const float* __restrict__ values)     // [NNZ]
{
    const int e = blockIdx.x * 256 + threadIdx.x;
    if (e >= NNZ) return;
    const int b = e / FEATS;
    const int f = e % FEATS;
    const unsigned cs = (unsigned)stm_idx [NNZ + e];
    const unsigned cn = (unsigned)nstm_idx[NNZ + e];
    const int dst = f * B_SZ + b;
    g_packed[dst] = cs | (cn << 16);
    g_vals[dst]   = __float2half(values[e]);
}

// ---------------------------------------------------------------------------
// Kernel 1: one CTA per (k-pair, column-half). 512 CTAs, 512 thr, 2 CTAs/SM.
// Phase A: fft_w rows {2kp, 2kp+1} -> smem pair-interleaved half2.
// Phase B: stream ft_w rows {2kp, 2kp+1}, cols [h*20480,(h+1)*20480),
//          fusing sfft2[c%640] -> sft2 (80 KB fp16 table).
// (PDL grid sync: wait for pack_idx_kernel here)
// Phase C: thread t = batch row t. Coalesced packed-index loads; one random
//          LDS.32 per in-range feature serves BOTH k's of the pair.
// ---------------------------------------------------------------------------
__global__ void __launch_bounds__(512, 2) halfkp_main_kernel(
    const float* __restrict__ ft_w,      // [512, 40960]
    const float* __restrict__ fft_w)     // [512, 640]
{
    extern __shared__ char smem_raw[];
    __half2* sft2  = reinterpret_cast<__half2*>(smem_raw);   // [HALF_C]
    __half2* sfft2 = sft2 + HALF_C;                          // [N_VFEAT]

    const int kp    = blockIdx.x >> 1;
    const int h     = blockIdx.x & 1;
    const int k0    = 2 * kp;
    const int cbase = h * HALF_C;
    const int t     = threadIdx.x;

    // ---- Phase A: fft rows pair-interleaved ----
    if (t < N_VFEAT / 4) {   // 160 threads, one float4 per row
        float4 a = __ldg(reinterpret_cast<const float4*>(
                             fft_w + (size_t)k0 * N_VFEAT) + t);
        float4 b = __ldg(reinterpret_cast<const float4*>(
                             fft_w + (size_t)(k0 + 1) * N_VFEAT) + t);
        uint4 p;
        p.x = h2u(__floats2half2_rn(a.x, b.x));
        p.y = h2u(__floats2half2_rn(a.y, b.y));
        p.z = h2u(__floats2half2_rn(a.z, b.z));
        p.w = h2u(__floats2half2_rn(a.w, b.w));
        reinterpret_cast<uint4*>(sfft2)[t] = p;
    }
    __syncthreads();

    // ---- Phase B: stream both rows' half, fuse fft, store pair half2 ----
    {
        const float4* r0 = reinterpret_cast<const float4*>(
                               ft_w + (size_t)k0 * N_FEAT + cbase);
        const float4* r1 = reinterpret_cast<const float4*>(
                               ft_w + (size_t)(k0 + 1) * N_FEAT + cbase);
        #pragma unroll
        for (int i = 0; i < HALF_C / 4 / 512; i++) {   // 10 iterations
            const int idx = t + i * 512;
            const int c   = idx * 4;                    // local col
            const int m   = c % N_VFEAT;                // HALF_C % 640 == 0
            float4 a = __ldg(r0 + idx);
            float4 b = __ldg(r1 + idx);
            uint4 p;
            p.x = h2u(__hadd2(__floats2half2_rn(a.x, b.x), sfft2[m + 0]));
            p.y = h2u(__hadd2(__floats2half2_rn(a.y, b.y), sfft2[m + 1]));
            p.z = h2u(__hadd2(__floats2half2_rn(a.z, b.z), sfft2[m + 2]));
            p.w = h2u(__hadd2(__floats2half2_rn(a.w, b.w), sfft2[m + 3]));
            *reinterpret_cast<uint4*>(sft2 + c) = p;
        }
    }
    __syncthreads();

    // PDL: ensure the pack prepass has finished before touching its output.
    cudaGridDependencySynchronize();

    // ---- Phase C: thread t = batch row t ----
    float2 accs = make_float2(0.f, 0.f);
    float2 accn = make_float2(0.f, 0.f);

    #pragma unroll
    for (int c = 0; c < 3; c++) {                       // chunks of 10 features
        unsigned p[10];
        __half   v[10];
        #pragma unroll
        for (int f = 0; f < 10; f++) {
            const int idx = (c * 10 + f) * B_SZ + t;    // lane-consecutive
            p[f] = __ldg(g_packed + idx);
            v[f] = g_vals[idx];
        }
        #pragma unroll
        for (int f = 0; f < 10; f++) {
            const float vf = __half2float(v[f]);
            const int ds = (int)(p[f] & 0xFFFFu) - cbase;
            const int dn = (int)(p[f] >> 16)     - cbase;
            if ((unsigned)ds < HALF_C) {
                float2 w = __half22float2(sft2[ds]);
                accs.x = fmaf(vf, w.x, accs.x);
                accs.y = fmaf(vf, w.y, accs.y);
            }
            if ((unsigned)dn < HALF_C) {
                float2 w = __half22float2(sft2[dn]);
                accn.x = fmaf(vf, w.x, accn.x);
                accn.y = fmaf(vf, w.y, accn.y);
            }
        }
    }

    g_accs[h][kp][t] = accs;    // coalesced float2 stores
    g_accn[h][kp][t] = accn;
}

// ---------------------------------------------------------------------------
// Kernel 2: combine halves, bias + clip + out_w dot + sigmoid.
// grid=16 blocks of (32 b-lanes x 8 kp-groups); all loads coalesced along b.
// Deterministic fixed-order summation.
// ---------------------------------------------------------------------------
__global__ void __launch_bounds__(256) halfkp_reduce_kernel(
    const float* __restrict__ ft_b,
    const float* __restrict__ fft_b,
    const float* __restrict__ out_w,     // [1, 1024]
    const float* __restrict__ out_b,
    float*       __restrict__ out)       // [512]
{
    const int tx = threadIdx.x & 31;     // batch lane
    const int ty = threadIdx.x >> 5;     // kp group (0..7)
    const int b  = blockIdx.x * 32 + tx;

    float part = 0.f;
    #pragma unroll 4
    for (int i = 0; i < KP / 8; i++) {   // 32 kp per group
        const int kp = ty * (KP / 8) + i;
        const int k0 = 2 * kp;

        float2 s0 = g_accs[0][kp][b];
        float2 s1 = g_accs[1][kp][b];
        float2 n0 = g_accn[0][kp][b];
        float2 n1 = g_accn[1][kp][b];

        const float b0 = __ldg(ft_b + k0)     + __ldg(fft_b + k0);
        const float b1 = __ldg(ft_b + k0 + 1) + __ldg(fft_b + k0 + 1);
        const float w0 = __ldg(out_w + k0);
        const float w1 = __ldg(out_w + k0 + 1);
        const float u0 = __ldg(out_w + FT_OUT + k0);
        const float u1 = __ldg(out_w + FT_OUT + k0 + 1);

        part += w0 * __saturatef(s0.x + s1.x + b0)
              + w1 * __saturatef(s0.y + s1.y + b1)
              + u0 * __saturatef(n0.x + n1.x + b0)
              + u1 * __saturatef(n0.y + n1.y + b1);
    }

    __shared__ float red[8][32];
    red[ty][tx] = part;
    __syncthreads();

    if (ty == 0) {
        float tot = __ldg(out_b);
        #pragma unroll
        for (int j = 0; j < 8; j++) tot += red[j][tx];
        out[b] = 1.0f / (1.0f + expf(-tot));
    }
}

// ---------------------------------------------------------------------------
extern "C" void kernel_launch(void* const* d_in, const int* in_sizes, int n_in,
                              void* d_out, int out_size) {
    const int*   stm_idx  = (const int*)  d_in[0];
    const int*   nstm_idx = (const int*)  d_in[1];
    const float* values   = (const float*)d_in[2];
    const float* ft_w     = (const float*)d_in[3];
    const float* ft_b     = (const float*)d_in[4];
    const float* fft_w    = (const float*)d_in[5];
    const float* fft_b    = (const float*)d_in[6];
    const float* out_w    = (const float*)d_in[7];
    const float* out_b    = (const float*)d_in[8];
    float*       out      = (float*)d_out;

    (void)in_sizes; (void)n_in; (void)out_size;

    cudaFuncSetAttribute(halfkp_main_kernel,
                         cudaFuncAttributeMaxDynamicSharedMemorySize, SMEM_BYTES);

    pack_idx_kernel<<<(NNZ + 255) / 256, 256>>>(stm_idx, nstm_idx, values);

    // Main kernel with Programmatic Dependent Launch: may start before the
    // pack kernel completes; it grid-syncs before Phase C reads packed data.
    {
        cudaLaunchConfig_t cfg = {};
        cfg.gridDim          = dim3(2 * KP);
        cfg.blockDim         = dim3(512);
        cfg.dynamicSmemBytes = SMEM_BYTES;
        cfg.stream           = 0;
        cudaLaunchAttribute at[1];
        at[0].id = cudaLaunchAttributeProgrammaticStreamSerialization;
        at[0].val.programmaticStreamSerializationAllowed = 1;
        cfg.attrs    = at;
        cfg.numAttrs = 1;
        cudaLaunchKernelEx(&cfg, halfkp_main_kernel, ft_w, fft_w);
    }

    halfkp_reduce_kernel<<<B_SZ / 32, 256>>>(ft_b, fft_b, out_w, out_b, out);
}